// round 9
// baseline (speedup 1.0000x reference)
#include <cuda_runtime.h>
#include <cuda_fp16.h>
#include <cstdint>

// ---------------- problem constants ----------------
#define NUM_EXPERTS 64
#define DIM 2048
#define HIDDEN 1024
#define TOK_PER_E 256
#define TOTAL_TOKENS (NUM_EXPERTS * TOK_PER_E)
#define NTHREADS 256

// scratch: fp16 fragment-packed x (64MB) and h (32MB)
__device__ uint4 g_xp[(size_t)TOTAL_TOKENS * DIM / 8];
__device__ uint4 g_hp[(size_t)TOTAL_TOKENS * HIDDEN / 8];

// ---------------- smem layout ----------------
// A: 3-stage ring of 16KB. B: 3-stage ring of 16KB.
#define A_PK 16384
#define B_BASE (3 * A_PK)                 // 49152
#define SMEM_TOT (B_BASE + 3 * 16384)     // 98304

// ---------------- helpers ----------------
__device__ __forceinline__ uint32_t smem_u32(const void* p) {
    uint32_t a;
    asm("{ .reg .u64 t; cvta.to.shared.u64 t, %1; cvt.u32.u64 %0, t; }" : "=r"(a) : "l"(p));
    return a;
}
__device__ __forceinline__ void cp_async16(uint32_t dst, const void* src) {
    asm volatile("cp.async.cg.shared.global [%0], [%1], 16;" :: "r"(dst), "l"(src));
}
__device__ __forceinline__ void cp_commit() {
    asm volatile("cp.async.commit_group;" ::: "memory");
}
template <int N>
__device__ __forceinline__ void cp_wait() {
    asm volatile("cp.async.wait_group %0;" :: "n"(N) : "memory");
}
__device__ __forceinline__ void mma_f16(float d[4], const uint32_t a[4],
                                        uint32_t b0, uint32_t b1) {
    asm volatile(
        "mma.sync.aligned.m16n8k16.row.col.f32.f16.f16.f32 "
        "{%0,%1,%2,%3}, {%4,%5,%6,%7}, {%8,%9}, {%0,%1,%2,%3};"
        : "+f"(d[0]), "+f"(d[1]), "+f"(d[2]), "+f"(d[3])
        : "r"(a[0]), "r"(a[1]), "r"(a[2]), "r"(a[3]), "r"(b0), "r"(b1));
}
__device__ __forceinline__ uint32_t packh2(float lo, float hi) {
    __half2 h = __floats2half2_rn(lo, hi);
    return *(uint32_t*)&h;
}
// B fragment word address (word units). lw = lane'*2 + slot (0..63).
__device__ __forceinline__ uint32_t bword(uint32_t f, uint32_t lw) {
    uint32_t swz = (((f >> 2) & 7) << 2) ^ (((f >> 5) & 1) << 1);
    return f * 64 + (lw ^ swz);
}
__device__ __forceinline__ void lds64(uint32_t& r0, uint32_t& r1, uint32_t addr) {
    asm volatile("ld.shared.v2.b32 {%0,%1}, [%2];" : "=r"(r0), "=r"(r1) : "r"(addr));
}

// ================= x pre-pass: fp32 -> fp16 fragment-packed =================
__global__ void xpack_kernel(const float* __restrict__ x, uint4* __restrict__ xp)
{
    const int it = blockIdx.x, mt = blockIdx.y, e = blockIdx.z, tid = threadIdx.x;
    const float* src = x + ((long long)e * TOK_PER_E + mt * 128) * DIM + it * 64;
    uint4* dst = xp + ((long long)(e * 2 + mt) * 32 + it) * 1024;
#pragma unroll
    for (int j = 0; j < 4; j++) {
        int fl = tid + 256 * j;
        int fA = fl >> 5, lane = fl & 31;
        int mt16 = fA >> 2, s = fA & 3, g = lane >> 2, c = lane & 3;
        const float* p = src + (long long)(mt16 * 16 + g) * DIM + s * 16 + 2 * c;
        float2 q0 = *(const float2*)p;
        float2 q1 = *(const float2*)(p + 8 * DIM);
        float2 q2 = *(const float2*)(p + 8);
        float2 q3 = *(const float2*)(p + 8 * DIM + 8);
        uint4 v;
        v.x = packh2(q0.x, q0.y);
        v.y = packh2(q1.x, q1.y);
        v.z = packh2(q2.x, q2.y);
        v.w = packh2(q3.x, q3.y);
        dst[fl] = v;
    }
}

// ================= fused gate/up + SiLU =================
// BM=128, BN=64 per matrix, BK=64. 8 warps: wm(4) x wn(2), warp tile 32x32 per matrix.
__global__ __launch_bounds__(NTHREADS, 2)
void moe_gateup(const uint4* __restrict__ xp, const float* __restrict__ w1,
                const float* __restrict__ w3, uint4* __restrict__ hp)
{
    extern __shared__ char smem[];
    const int tid = threadIdx.x, lane = tid & 31, wid = tid >> 5;
    const int wm = wid >> 1, wn = wid & 1;
    const int e = blockIdx.z, mt = blockIdx.y, nt = blockIdx.x;

    const uint4* xpe = xp + (long long)(e * 2 + mt) * 32 * 1024;
    const float* w1e = w1 + (long long)e * DIM * HIDDEN + nt * 64;
    const float* w3e = w3 + (long long)e * DIM * HIDDEN + nt * 64;

    uint32_t s1[8], s3[8];  // staged half2 words

    auto ldgB = [&](int kt) {
#pragma unroll
        for (int j = 0; j < 2; j++) {
            int id = tid + 256 * j;
            int m = id >> 4, c4 = id & 15;
            const float* p1 = w1e + (long long)(kt + 2 * m) * HIDDEN + 4 * c4;
            float4 r0 = *(const float4*)p1;
            float4 r1 = *(const float4*)(p1 + HIDDEN);
            s1[j * 4 + 0] = packh2(r0.x, r1.x);
            s1[j * 4 + 1] = packh2(r0.y, r1.y);
            s1[j * 4 + 2] = packh2(r0.z, r1.z);
            s1[j * 4 + 3] = packh2(r0.w, r1.w);
            const float* p3 = w3e + (long long)(kt + 2 * m) * HIDDEN + 4 * c4;
            float4 t0 = *(const float4*)p3;
            float4 t1 = *(const float4*)(p3 + HIDDEN);
            s3[j * 4 + 0] = packh2(t0.x, t1.x);
            s3[j * 4 + 1] = packh2(t0.y, t1.y);
            s3[j * 4 + 2] = packh2(t0.z, t1.z);
            s3[j * 4 + 3] = packh2(t0.w, t1.w);
        }
    };
    auto stsB = [&](int buf) {
        uint32_t* b1 = (uint32_t*)(smem + B_BASE + buf * 16384);
        uint32_t* b3 = b1 + 2048;
#pragma unroll
        for (int j = 0; j < 2; j++) {
            int id = tid + 256 * j;
            int m = id >> 4, c4 = id & 15;
            uint32_t f = (uint32_t)(c4 >> 1) * 4 + (m >> 3);
            uint32_t slot = (m >> 2) & 1;
#pragma unroll
            for (int i = 0; i < 4; i++) {
                uint32_t lp = (uint32_t)(4 * (c4 & 1) + i) * 4 + (m & 3);
                uint32_t w = bword(f, lp * 2 + slot);
                b1[w] = s1[j * 4 + i];
                b3[w] = s3[j * 4 + i];
            }
        }
    };
    auto ldA = [&](int stage, int buf) {
        uint32_t sA = smem_u32(smem) + buf * A_PK;
        const uint4* src = xpe + (long long)stage * 1024;
#pragma unroll
        for (int j = 0; j < 4; j++) {
            int idx = tid + 256 * j;
            cp_async16(sA + idx * 16, src + idx);
        }
        cp_commit();
    };

    float accG[2][4][4] = {}, accU[2][4][4] = {};

    // prologue: B bufs 0,1 filled; regs hold stage 2; A stages 0,1 in flight
    ldgB(0);
    ldA(0, 0);
    ldA(1, 1);
    stsB(0);
    ldgB(64);
    stsB(1);
    ldgB(128);
    cp_wait<1>();
    __syncthreads();

    const int NIT = DIM / 64;  // 32
    int a3 = 0, a3n = 2;
    int bW = 2;                // B buf to write (stage it+2)
    for (int it = 0; it < NIT; ++it) {
        if (it + 2 < NIT) stsB(bW);          // overlapped with compute below
        if (it + 3 < NIT) ldgB((it + 3) * 64);
        if (it + 2 < NIT) ldA(it + 2, a3n);

        const uint4* Ap = (const uint4*)(smem + a3 * A_PK);
        const uint32_t bR = (bW == 2) ? 0 : bW + 1;   // (it)%3
        const uint32_t B1base = smem_u32(smem) + B_BASE + bR * 16384;
        const uint32_t B3base = B1base + 8192;

#pragma unroll
        for (int s = 0; s < 4; s++) {
            uint32_t a[2][4];
            {
                uint4 t0 = Ap[((2 * wm + 0) * 4 + s) * 32 + lane];
                uint4 t1 = Ap[((2 * wm + 1) * 4 + s) * 32 + lane];
                a[0][0] = t0.x; a[0][1] = t0.y; a[0][2] = t0.z; a[0][3] = t0.w;
                a[1][0] = t1.x; a[1][1] = t1.y; a[1][2] = t1.z; a[1][3] = t1.w;
            }
#pragma unroll
            for (int ni = 0; ni < 4; ni++) {
                uint32_t f = (uint32_t)(wn * 4 + ni) * 4 + s;
                uint32_t woff = bword(f, (uint32_t)lane * 2) * 4;
                uint32_t b0, b1v;
                lds64(b0, b1v, B1base + woff);
                mma_f16(accG[0][ni], a[0], b0, b1v);
                mma_f16(accG[1][ni], a[1], b0, b1v);
                uint32_t c0, c1v;
                lds64(c0, c1v, B3base + woff);
                mma_f16(accU[0][ni], a[0], c0, c1v);
                mma_f16(accU[1][ni], a[1], c0, c1v);
            }
        }
        if (it + 1 < NIT) {
            if (it + 2 < NIT) cp_wait<1>(); else cp_wait<0>();
            __syncthreads();
        }
        a3 = (a3 == 2) ? 0 : a3 + 1;
        a3n = (a3n == 2) ? 0 : a3n + 1;
        bW = (bW == 2) ? 0 : bW + 1;
    }

    // epilogue: h = silu(gate)*up -> fp16, fragment-packed, coalesced uint4 stores
    uint4* hpe = hp + ((long long)(e * 2 + mt) * 16 + nt) * 1024;
#pragma unroll
    for (int mi = 0; mi < 2; mi++) {
#pragma unroll
        for (int nip = 0; nip < 2; nip++) {
            float hv[2][4];
#pragma unroll
            for (int q = 0; q < 2; q++) {
                int ni = 2 * nip + q;
#pragma unroll
                for (int j = 0; j < 4; j++) {
                    float gv = accG[mi][ni][j], uv = accU[mi][ni][j];
                    hv[q][j] = gv / (1.f + __expf(-gv)) * uv;
                }
            }
            uint4 v;
            v.x = packh2(hv[0][0], hv[0][1]);
            v.y = packh2(hv[0][2], hv[0][3]);
            v.z = packh2(hv[1][0], hv[1][1]);
            v.w = packh2(hv[1][2], hv[1][3]);
            int f_dn = (wm * 2 + mi) * 4 + (wn * 2 + nip);
            hpe[f_dn * 32 + lane] = v;
        }
    }
}

// ================= down-projection =================
// BM=128, BN=128, BK=64. Warp tile 32x64.
__global__ __launch_bounds__(NTHREADS, 2)
void moe_down(const uint4* __restrict__ hp, const float* __restrict__ w2,
              float* __restrict__ out)
{
    extern __shared__ char smem[];
    const int tid = threadIdx.x, lane = tid & 31, wid = tid >> 5;
    const int wm = wid >> 1, wn = wid & 1, g = lane >> 2, c = lane & 3;
    const int e = blockIdx.z, mt = blockIdx.y, nt = blockIdx.x;

    const uint4* hpe = hp + (long long)(e * 2 + mt) * 16 * 1024;
    const float* w2e = w2 + (long long)e * HIDDEN * DIM + nt * 128;

    uint32_t sw[16];  // staged half2 words

    auto ldgB = [&](int kt) {
#pragma unroll
        for (int j = 0; j < 4; j++) {
            int id = tid + 256 * j;
            int m = id >> 5, c4 = id & 31;
            const float* p = w2e + (long long)(kt + 2 * m) * DIM + 4 * c4;
            float4 r0 = *(const float4*)p;
            float4 r1 = *(const float4*)(p + DIM);
            sw[j * 4 + 0] = packh2(r0.x, r1.x);
            sw[j * 4 + 1] = packh2(r0.y, r1.y);
            sw[j * 4 + 2] = packh2(r0.z, r1.z);
            sw[j * 4 + 3] = packh2(r0.w, r1.w);
        }
    };
    auto stsB = [&](int buf) {
        uint32_t* bb = (uint32_t*)(smem + B_BASE + buf * 16384);
#pragma unroll
        for (int j = 0; j < 4; j++) {
            int id = tid + 256 * j;
            int m = id >> 5, c4 = id & 31;
            uint32_t f = (uint32_t)(c4 >> 1) * 4 + (m >> 3);
            uint32_t slot = (m >> 2) & 1;
#pragma unroll
            for (int i = 0; i < 4; i++) {
                uint32_t lp = (uint32_t)(4 * (c4 & 1) + i) * 4 + (m & 3);
                bb[bword(f, lp * 2 + slot)] = sw[j * 4 + i];
            }
        }
    };
    auto ldA = [&](int stage, int buf) {
        uint32_t sA = smem_u32(smem) + buf * A_PK;
        const uint4* src = hpe + (long long)stage * 1024;
#pragma unroll
        for (int j = 0; j < 4; j++) {
            int idx = tid + 256 * j;
            cp_async16(sA + idx * 16, src + idx);
        }
        cp_commit();
    };

    float acc[2][8][4] = {};

    ldgB(0);
    ldA(0, 0);
    ldA(1, 1);
    stsB(0);
    ldgB(64);
    stsB(1);
    ldgB(128);
    cp_wait<1>();
    __syncthreads();

    const int NIT = HIDDEN / 64;  // 16
    int a3 = 0, a3n = 2;
    int bW = 2;
    for (int it = 0; it < NIT; ++it) {
        if (it + 2 < NIT) stsB(bW);
        if (it + 3 < NIT) ldgB((it + 3) * 64);
        if (it + 2 < NIT) ldA(it + 2, a3n);

        const uint4* Ap = (const uint4*)(smem + a3 * A_PK);
        const uint32_t bR = (bW == 2) ? 0 : bW + 1;
        const uint32_t Bbase = smem_u32(smem) + B_BASE + bR * 16384;

#pragma unroll
        for (int s = 0; s < 4; s++) {
            uint32_t a[2][4];
            {
                uint4 t0 = Ap[((2 * wm + 0) * 4 + s) * 32 + lane];
                uint4 t1 = Ap[((2 * wm + 1) * 4 + s) * 32 + lane];
                a[0][0] = t0.x; a[0][1] = t0.y; a[0][2] = t0.z; a[0][3] = t0.w;
                a[1][0] = t1.x; a[1][1] = t1.y; a[1][2] = t1.z; a[1][3] = t1.w;
            }
#pragma unroll
            for (int ni = 0; ni < 8; ni++) {
                uint32_t f = (uint32_t)(wn * 8 + ni) * 4 + s;
                uint32_t b0, b1v;
                lds64(b0, b1v, Bbase + bword(f, (uint32_t)lane * 2) * 4);
                mma_f16(acc[0][ni], a[0], b0, b1v);
                mma_f16(acc[1][ni], a[1], b0, b1v);
            }
        }
        if (it + 1 < NIT) {
            if (it + 2 < NIT) cp_wait<1>(); else cp_wait<0>();
            __syncthreads();
        }
        a3 = (a3 == 2) ? 0 : a3 + 1;
        a3n = (a3n == 2) ? 0 : a3n + 1;
        bW = (bW == 2) ? 0 : bW + 1;
    }

    const int colbase = nt * 128 + wn * 64;
    const long long rowbase = (long long)e * TOK_PER_E + mt * 128 + wm * 32;
#pragma unroll
    for (int mi = 0; mi < 2; mi++) {
        const long long r0 = rowbase + mi * 16 + g;
#pragma unroll
        for (int ni = 0; ni < 8; ni++) {
            const int col = colbase + ni * 8 + 2 * c;
            float* p0 = out + r0 * DIM + col;
            float* p1 = p0 + 8 * DIM;
            *(float2*)p0 = make_float2(acc[mi][ni][0], acc[mi][ni][1]);
            *(float2*)p1 = make_float2(acc[mi][ni][2], acc[mi][ni][3]);
        }
    }
}

// ================= launch =================
extern "C" void kernel_launch(void* const* d_in, const int* in_sizes, int n_in,
                              void* d_out, int out_size)
{
    const float* x  = (const float*)d_in[0];
    const float* w1 = (const float*)d_in[1];
    const float* w2 = (const float*)d_in[2];
    const float* w3 = (const float*)d_in[3];
    float* out = (float*)d_out;

    uint4* xp = nullptr;
    uint4* hp = nullptr;
    cudaGetSymbolAddress((void**)&xp, g_xp);
    cudaGetSymbolAddress((void**)&hp, g_hp);

    static bool attr_done = false;
    if (!attr_done) {
        cudaFuncSetAttribute(moe_gateup, cudaFuncAttributeMaxDynamicSharedMemorySize, SMEM_TOT);
        cudaFuncSetAttribute(moe_down, cudaFuncAttributeMaxDynamicSharedMemorySize, SMEM_TOT);
        attr_done = true;
    }

    {
        dim3 grid(DIM / 64, TOK_PER_E / 128, NUM_EXPERTS);     // (32, 2, 64)
        xpack_kernel<<<grid, NTHREADS>>>(x, xp);
    }
    {
        dim3 grid(HIDDEN / 64, TOK_PER_E / 128, NUM_EXPERTS);  // (16, 2, 64)
        moe_gateup<<<grid, NTHREADS, SMEM_TOT>>>(xp, w1, w3, hp);
    }
    {
        dim3 grid(DIM / 128, TOK_PER_E / 128, NUM_EXPERTS);    // (16, 2, 64)
        moe_down<<<grid, NTHREADS, SMEM_TOT>>>(hp, w2, out);
    }
}

// round 11
// speedup vs baseline: 1.0445x; 1.0445x over previous
#include <cuda_runtime.h>
#include <cuda_fp16.h>
#include <cstdint>

// ---------------- problem constants ----------------
#define NUM_EXPERTS 64
#define DIM 2048
#define HIDDEN 1024
#define TOK_PER_E 256
#define TOTAL_TOKENS (NUM_EXPERTS * TOK_PER_E)
#define NTHREADS 256

// scratch: fp16 fragment-packed x (64MB) and h (32MB)
__device__ uint4 g_xp[(size_t)TOTAL_TOKENS * DIM / 8];
__device__ uint4 g_hp[(size_t)TOTAL_TOKENS * HIDDEN / 8];

// ---------------- smem layout ----------------
// A stage: 16KB, 3-stage ring. B stage: 16KB, 2-stage.
#define A_PK 16384
#define B_BASE (3 * A_PK)                // 49152
#define SMEM_TOT (B_BASE + 2 * 16384)    // 81920

// ---------------- helpers ----------------
__device__ __forceinline__ uint32_t smem_u32(const void* p) {
    uint32_t a;
    asm("{ .reg .u64 t; cvta.to.shared.u64 t, %1; cvt.u32.u64 %0, t; }" : "=r"(a) : "l"(p));
    return a;
}
__device__ __forceinline__ void cp_async16(uint32_t dst, const void* src) {
    asm volatile("cp.async.cg.shared.global [%0], [%1], 16;" :: "r"(dst), "l"(src));
}
__device__ __forceinline__ void cp_commit() {
    asm volatile("cp.async.commit_group;" ::: "memory");
}
template <int N>
__device__ __forceinline__ void cp_wait() {
    asm volatile("cp.async.wait_group %0;" :: "n"(N) : "memory");
}
__device__ __forceinline__ void mma_f16(float d[4], const uint32_t a[4],
                                        uint32_t b0, uint32_t b1) {
    asm volatile(
        "mma.sync.aligned.m16n8k16.row.col.f32.f16.f16.f32 "
        "{%0,%1,%2,%3}, {%4,%5,%6,%7}, {%8,%9}, {%0,%1,%2,%3};"
        : "+f"(d[0]), "+f"(d[1]), "+f"(d[2]), "+f"(d[3])
        : "r"(a[0]), "r"(a[1]), "r"(a[2]), "r"(a[3]), "r"(b0), "r"(b1));
}
__device__ __forceinline__ uint32_t packh2(float lo, float hi) {
    __half2 h = __floats2half2_rn(lo, hi);
    return *(uint32_t*)&h;
}
// B fragment word address (word units). lw = lane'*2 + slot (0..63).
__device__ __forceinline__ uint32_t bword(uint32_t f, uint32_t lw) {
    uint32_t swz = (((f >> 2) & 7) << 2) ^ (((f >> 5) & 1) << 1);
    return f * 64 + (lw ^ swz);
}
__device__ __forceinline__ void lds64(uint32_t& r0, uint32_t& r1, uint32_t addr) {
    asm volatile("ld.shared.v2.b32 {%0,%1}, [%2];" : "=r"(r0), "=r"(r1) : "r"(addr));
}

// ================= x pre-pass: fp32 -> fp16 fragment-packed =================
__global__ void xpack_kernel(const float* __restrict__ x, uint4* __restrict__ xp)
{
    const int it = blockIdx.x, mt = blockIdx.y, e = blockIdx.z, tid = threadIdx.x;
    const float* src = x + ((long long)e * TOK_PER_E + mt * 128) * DIM + it * 64;
    uint4* dst = xp + ((long long)(e * 2 + mt) * 32 + it) * 1024;
#pragma unroll
    for (int j = 0; j < 4; j++) {
        int fl = tid + 256 * j;
        int fA = fl >> 5, lane = fl & 31;
        int mt16 = fA >> 2, s = fA & 3, g = lane >> 2, c = lane & 3;
        const float* p = src + (long long)(mt16 * 16 + g) * DIM + s * 16 + 2 * c;
        float2 q0 = *(const float2*)p;
        float2 q1 = *(const float2*)(p + 8 * DIM);
        float2 q2 = *(const float2*)(p + 8);
        float2 q3 = *(const float2*)(p + 8 * DIM + 8);
        uint4 v;
        v.x = packh2(q0.x, q0.y);
        v.y = packh2(q1.x, q1.y);
        v.z = packh2(q2.x, q2.y);
        v.w = packh2(q3.x, q3.y);
        dst[fl] = v;
    }
}

// ================= fused gate/up + SiLU =================
// BM=128, BN=64 per matrix, BK=64. 8 warps: wm(4) x wn(2), warp tile 32x32 per matrix.
__global__ __launch_bounds__(NTHREADS, 2)
void moe_gateup(const uint4* __restrict__ xp, const float* __restrict__ w1,
                const float* __restrict__ w3, uint4* __restrict__ hp)
{
    extern __shared__ char smem[];
    const int tid = threadIdx.x, lane = tid & 31, wid = tid >> 5;
    const int wm = wid >> 1, wn = wid & 1;
    const int e = blockIdx.z, mt = blockIdx.y, nt = blockIdx.x;

    const uint4* xpe = xp + (long long)(e * 2 + mt) * 32 * 1024;
    const float* w1e = w1 + (long long)e * DIM * HIDDEN + nt * 64;
    const float* w3e = w3 + (long long)e * DIM * HIDDEN + nt * 64;

    uint32_t s1[8], s3[8];  // staged half2 words

    auto ldgB = [&](int kt) {
#pragma unroll
        for (int j = 0; j < 2; j++) {
            int id = tid + 256 * j;
            int m = id >> 4, c4 = id & 15;
            const float* p1 = w1e + (long long)(kt + 2 * m) * HIDDEN + 4 * c4;
            float4 r0 = *(const float4*)p1;
            float4 r1 = *(const float4*)(p1 + HIDDEN);
            s1[j * 4 + 0] = packh2(r0.x, r1.x);
            s1[j * 4 + 1] = packh2(r0.y, r1.y);
            s1[j * 4 + 2] = packh2(r0.z, r1.z);
            s1[j * 4 + 3] = packh2(r0.w, r1.w);
            const float* p3 = w3e + (long long)(kt + 2 * m) * HIDDEN + 4 * c4;
            float4 t0 = *(const float4*)p3;
            float4 t1 = *(const float4*)(p3 + HIDDEN);
            s3[j * 4 + 0] = packh2(t0.x, t1.x);
            s3[j * 4 + 1] = packh2(t0.y, t1.y);
            s3[j * 4 + 2] = packh2(t0.z, t1.z);
            s3[j * 4 + 3] = packh2(t0.w, t1.w);
        }
    };
    auto stsB = [&](int buf) {
        uint32_t* b1 = (uint32_t*)(smem + B_BASE + buf * 16384);
        uint32_t* b3 = b1 + 2048;
#pragma unroll
        for (int j = 0; j < 2; j++) {
            int id = tid + 256 * j;
            int m = id >> 4, c4 = id & 15;
            uint32_t f = (uint32_t)(c4 >> 1) * 4 + (m >> 3);
            uint32_t slot = (m >> 2) & 1;
#pragma unroll
            for (int i = 0; i < 4; i++) {
                uint32_t lp = (uint32_t)(4 * (c4 & 1) + i) * 4 + (m & 3);
                uint32_t w = bword(f, lp * 2 + slot);
                b1[w] = s1[j * 4 + i];
                b3[w] = s3[j * 4 + i];
            }
        }
    };
    auto ldA = [&](int stage, int buf) {
        uint32_t sA = smem_u32(smem) + buf * A_PK;
        const uint4* src = xpe + (long long)stage * 1024;
#pragma unroll
        for (int j = 0; j < 4; j++) {
            int idx = tid + 256 * j;
            cp_async16(sA + idx * 16, src + idx);
        }
        cp_commit();
    };

    float accG[2][4][4] = {}, accU[2][4][4] = {};

    ldgB(0);
    ldA(0, 0);
    ldA(1, 1);
    stsB(0);
    ldgB(64);
    cp_wait<1>();
    __syncthreads();

    const int NIT = DIM / 64;  // 32
    int a3 = 0, a3n = 2;
    for (int it = 0; it < NIT; ++it) {
        const int b = it & 1;
        if (it + 2 < NIT) ldA(it + 2, a3n);

        const uint4* Ap = (const uint4*)(smem + a3 * A_PK);
        const uint32_t B1base = smem_u32(smem) + B_BASE + b * 16384;
        const uint32_t B3base = B1base + 8192;

#pragma unroll
        for (int s = 0; s < 4; s++) {
            uint32_t a[2][4];
            {
                uint4 t0 = Ap[((2 * wm + 0) * 4 + s) * 32 + lane];
                uint4 t1 = Ap[((2 * wm + 1) * 4 + s) * 32 + lane];
                a[0][0] = t0.x; a[0][1] = t0.y; a[0][2] = t0.z; a[0][3] = t0.w;
                a[1][0] = t1.x; a[1][1] = t1.y; a[1][2] = t1.z; a[1][3] = t1.w;
            }
#pragma unroll
            for (int ni = 0; ni < 4; ni++) {
                uint32_t f = (uint32_t)(wn * 4 + ni) * 4 + s;
                uint32_t woff = bword(f, (uint32_t)lane * 2) * 4;
                // issue both B loads before their MMA block (load-use slack)
                uint32_t b0, b1v, c0, c1v;
                lds64(b0, b1v, B1base + woff);
                lds64(c0, c1v, B3base + woff);
                mma_f16(accG[0][ni], a[0], b0, b1v);
                mma_f16(accG[1][ni], a[1], b0, b1v);
                mma_f16(accU[0][ni], a[0], c0, c1v);
                mma_f16(accU[1][ni], a[1], c0, c1v);
            }
        }
        if (it + 1 < NIT) stsB(1 - b);
        if (it + 2 < NIT) { ldgB((it + 2) * 64); cp_wait<1>(); }
        else cp_wait<0>();
        if (it + 1 < NIT) __syncthreads();
        a3 = (a3 == 2) ? 0 : a3 + 1;
        a3n = (a3n == 2) ? 0 : a3n + 1;
    }

    // epilogue: h = silu(gate)*up -> fp16, fragment-packed, coalesced uint4 stores
    uint4* hpe = hp + ((long long)(e * 2 + mt) * 16 + nt) * 1024;
#pragma unroll
    for (int mi = 0; mi < 2; mi++) {
#pragma unroll
        for (int nip = 0; nip < 2; nip++) {
            float hv[2][4];
#pragma unroll
            for (int q = 0; q < 2; q++) {
                int ni = 2 * nip + q;
#pragma unroll
                for (int j = 0; j < 4; j++) {
                    float gv = accG[mi][ni][j], uv = accU[mi][ni][j];
                    hv[q][j] = gv / (1.f + __expf(-gv)) * uv;
                }
            }
            uint4 v;
            v.x = packh2(hv[0][0], hv[0][1]);
            v.y = packh2(hv[0][2], hv[0][3]);
            v.z = packh2(hv[1][0], hv[1][1]);
            v.w = packh2(hv[1][2], hv[1][3]);
            int f_dn = (wm * 2 + mi) * 4 + (wn * 2 + nip);
            hpe[f_dn * 32 + lane] = v;
        }
    }
}

// ================= down-projection =================
// BM=128, BN=128, BK=64. Warp tile 32x64.
__global__ __launch_bounds__(NTHREADS, 2)
void moe_down(const uint4* __restrict__ hp, const float* __restrict__ w2,
              float* __restrict__ out)
{
    extern __shared__ char smem[];
    const int tid = threadIdx.x, lane = tid & 31, wid = tid >> 5;
    const int wm = wid >> 1, wn = wid & 1, g = lane >> 2, c = lane & 3;
    const int e = blockIdx.z, mt = blockIdx.y, nt = blockIdx.x;

    const uint4* hpe = hp + (long long)(e * 2 + mt) * 16 * 1024;
    const float* w2e = w2 + (long long)e * HIDDEN * DIM + nt * 128;

    uint32_t sw[16];  // staged half2 words

    auto ldgB = [&](int kt) {
#pragma unroll
        for (int j = 0; j < 4; j++) {
            int id = tid + 256 * j;
            int m = id >> 5, c4 = id & 31;
            const float* p = w2e + (long long)(kt + 2 * m) * DIM + 4 * c4;
            float4 r0 = *(const float4*)p;
            float4 r1 = *(const float4*)(p + DIM);
            sw[j * 4 + 0] = packh2(r0.x, r1.x);
            sw[j * 4 + 1] = packh2(r0.y, r1.y);
            sw[j * 4 + 2] = packh2(r0.z, r1.z);
            sw[j * 4 + 3] = packh2(r0.w, r1.w);
        }
    };
    auto stsB = [&](int buf) {
        uint32_t* bb = (uint32_t*)(smem + B_BASE + buf * 16384);
#pragma unroll
        for (int j = 0; j < 4; j++) {
            int id = tid + 256 * j;
            int m = id >> 5, c4 = id & 31;
            uint32_t f = (uint32_t)(c4 >> 1) * 4 + (m >> 3);
            uint32_t slot = (m >> 2) & 1;
#pragma unroll
            for (int i = 0; i < 4; i++) {
                uint32_t lp = (uint32_t)(4 * (c4 & 1) + i) * 4 + (m & 3);
                bb[bword(f, lp * 2 + slot)] = sw[j * 4 + i];
            }
        }
    };
    auto ldA = [&](int stage, int buf) {
        uint32_t sA = smem_u32(smem) + buf * A_PK;
        const uint4* src = hpe + (long long)stage * 1024;
#pragma unroll
        for (int j = 0; j < 4; j++) {
            int idx = tid + 256 * j;
            cp_async16(sA + idx * 16, src + idx);
        }
        cp_commit();
    };

    float acc[2][8][4] = {};

    ldgB(0);
    ldA(0, 0);
    ldA(1, 1);
    stsB(0);
    ldgB(64);
    cp_wait<1>();
    __syncthreads();

    const int NIT = HIDDEN / 64;  // 16
    int a3 = 0, a3n = 2;
    for (int it = 0; it < NIT; ++it) {
        const int b = it & 1;
        if (it + 2 < NIT) ldA(it + 2, a3n);

        const uint4* Ap = (const uint4*)(smem + a3 * A_PK);
        const uint32_t Bbase = smem_u32(smem) + B_BASE + b * 16384;

#pragma unroll
        for (int s = 0; s < 4; s++) {
            uint32_t a[2][4];
            {
                uint4 t0 = Ap[((2 * wm + 0) * 4 + s) * 32 + lane];
                uint4 t1 = Ap[((2 * wm + 1) * 4 + s) * 32 + lane];
                a[0][0] = t0.x; a[0][1] = t0.y; a[0][2] = t0.z; a[0][3] = t0.w;
                a[1][0] = t1.x; a[1][1] = t1.y; a[1][2] = t1.z; a[1][3] = t1.w;
            }
#pragma unroll
            for (int nip = 0; nip < 4; nip++) {
                // pair up two ni's: both loads first, then 4 MMAs
                uint32_t f0 = (uint32_t)(wn * 8 + 2 * nip) * 4 + s;
                uint32_t f1 = f0 + 4;
                uint32_t b0, b1v, c0, c1v;
                lds64(b0, b1v, Bbase + bword(f0, (uint32_t)lane * 2) * 4);
                lds64(c0, c1v, Bbase + bword(f1, (uint32_t)lane * 2) * 4);
                mma_f16(acc[0][2 * nip], a[0], b0, b1v);
                mma_f16(acc[1][2 * nip], a[1], b0, b1v);
                mma_f16(acc[0][2 * nip + 1], a[0], c0, c1v);
                mma_f16(acc[1][2 * nip + 1], a[1], c0, c1v);
            }
        }
        if (it + 1 < NIT) stsB(1 - b);
        if (it + 2 < NIT) { ldgB((it + 2) * 64); cp_wait<1>(); }
        else cp_wait<0>();
        if (it + 1 < NIT) __syncthreads();
        a3 = (a3 == 2) ? 0 : a3 + 1;
        a3n = (a3n == 2) ? 0 : a3n + 1;
    }

    const int colbase = nt * 128 + wn * 64;
    const long long rowbase = (long long)e * TOK_PER_E + mt * 128 + wm * 32;
#pragma unroll
    for (int mi = 0; mi < 2; mi++) {
        const long long r0 = rowbase + mi * 16 + g;
#pragma unroll
        for (int ni = 0; ni < 8; ni++) {
            const int col = colbase + ni * 8 + 2 * c;
            float* p0 = out + r0 * DIM + col;
            float* p1 = p0 + 8 * DIM;
            *(float2*)p0 = make_float2(acc[mi][ni][0], acc[mi][ni][1]);
            *(float2*)p1 = make_float2(acc[mi][ni][2], acc[mi][ni][3]);
        }
    }
}

// ================= launch =================
extern "C" void kernel_launch(void* const* d_in, const int* in_sizes, int n_in,
                              void* d_out, int out_size)
{
    const float* x  = (const float*)d_in[0];
    const float* w1 = (const float*)d_in[1];
    const float* w2 = (const float*)d_in[2];
    const float* w3 = (const float*)d_in[3];
    float* out = (float*)d_out;

    uint4* xp = nullptr;
    uint4* hp = nullptr;
    cudaGetSymbolAddress((void**)&xp, g_xp);
    cudaGetSymbolAddress((void**)&hp, g_hp);

    static bool attr_done = false;
    if (!attr_done) {
        cudaFuncSetAttribute(moe_gateup, cudaFuncAttributeMaxDynamicSharedMemorySize, SMEM_TOT);
        cudaFuncSetAttribute(moe_down, cudaFuncAttributeMaxDynamicSharedMemorySize, SMEM_TOT);
        attr_done = true;
    }

    {
        dim3 grid(DIM / 64, TOK_PER_E / 128, NUM_EXPERTS);     // (32, 2, 64)
        xpack_kernel<<<grid, NTHREADS>>>(x, xp);
    }
    {
        dim3 grid(HIDDEN / 64, TOK_PER_E / 128, NUM_EXPERTS);  // (16, 2, 64)
        moe_gateup<<<grid, NTHREADS, SMEM_TOT>>>(xp, w1, w3, hp);
    }
    {
        dim3 grid(DIM / 128, TOK_PER_E / 128, NUM_EXPERTS);    // (16, 2, 64)
        moe_down<<<grid, NTHREADS, SMEM_TOT>>>(hp, w2, out);
    }
}

// round 13
// speedup vs baseline: 1.2453x; 1.1923x over previous
#include <cuda_runtime.h>
#include <cuda_fp16.h>
#include <cstdint>

// ---------------- problem constants ----------------
#define NUM_EXPERTS 64
#define DIM 2048
#define HIDDEN 1024
#define TOK_PER_E 256
#define TOTAL_TOKENS (NUM_EXPERTS * TOK_PER_E)
#define NTHREADS 256

// scratch: fp16 fragment-packed x (64MB) and h (32MB)
__device__ uint4 g_xp[(size_t)TOTAL_TOKENS * DIM / 8];
__device__ uint4 g_hp[(size_t)TOTAL_TOKENS * HIDDEN / 8];

// ---------------- smem layout ----------------
// A stage: 16KB, 3-stage ring. B stage: 16KB, 2-stage.
#define A_PK 16384
#define B_BASE (3 * A_PK)                // 49152
#define SMEM_TOT (B_BASE + 2 * 16384)    // 81920

// ---------------- helpers ----------------
__device__ __forceinline__ uint32_t smem_u32(const void* p) {
    uint32_t a;
    asm("{ .reg .u64 t; cvta.to.shared.u64 t, %1; cvt.u32.u64 %0, t; }" : "=r"(a) : "l"(p));
    return a;
}
__device__ __forceinline__ void cp_async16(uint32_t dst, const void* src) {
    asm volatile("cp.async.cg.shared.global [%0], [%1], 16;" :: "r"(dst), "l"(src));
}
__device__ __forceinline__ void cp_commit() {
    asm volatile("cp.async.commit_group;" ::: "memory");
}
template <int N>
__device__ __forceinline__ void cp_wait() {
    asm volatile("cp.async.wait_group %0;" :: "n"(N) : "memory");
}
__device__ __forceinline__ void mma_f16(float d[4], const uint32_t a[4],
                                        uint32_t b0, uint32_t b1) {
    asm volatile(
        "mma.sync.aligned.m16n8k16.row.col.f32.f16.f16.f32 "
        "{%0,%1,%2,%3}, {%4,%5,%6,%7}, {%8,%9}, {%0,%1,%2,%3};"
        : "+f"(d[0]), "+f"(d[1]), "+f"(d[2]), "+f"(d[3])
        : "r"(a[0]), "r"(a[1]), "r"(a[2]), "r"(a[3]), "r"(b0), "r"(b1));
}
__device__ __forceinline__ uint32_t packh2(float lo, float hi) {
    __half2 h = __floats2half2_rn(lo, hi);
    return *(uint32_t*)&h;
}
// ldmatrix x4 transposed (B operand from k-major [k][n] smem rows)
__device__ __forceinline__ void ldm_x4t(uint32_t& r0, uint32_t& r1,
                                        uint32_t& r2, uint32_t& r3, uint32_t addr) {
    asm volatile("ldmatrix.sync.aligned.m8n8.x4.trans.shared.b16 {%0,%1,%2,%3}, [%4];"
                 : "=r"(r0), "=r"(r1), "=r"(r2), "=r"(r3) : "r"(addr));
}

// ================= x pre-pass: fp32 -> fp16 fragment-packed =================
__global__ void xpack_kernel(const float* __restrict__ x, uint4* __restrict__ xp)
{
    const int it = blockIdx.x, mt = blockIdx.y, e = blockIdx.z, tid = threadIdx.x;
    const float* src = x + ((long long)e * TOK_PER_E + mt * 128) * DIM + it * 64;
    uint4* dst = xp + ((long long)(e * 2 + mt) * 32 + it) * 1024;
#pragma unroll
    for (int j = 0; j < 4; j++) {
        int fl = tid + 256 * j;
        int fA = fl >> 5, lane = fl & 31;
        int mt16 = fA >> 2, s = fA & 3, g = lane >> 2, c = lane & 3;
        const float* p = src + (long long)(mt16 * 16 + g) * DIM + s * 16 + 2 * c;
        float2 q0 = *(const float2*)p;
        float2 q1 = *(const float2*)(p + 8 * DIM);
        float2 q2 = *(const float2*)(p + 8);
        float2 q3 = *(const float2*)(p + 8 * DIM + 8);
        uint4 v;
        v.x = packh2(q0.x, q0.y);
        v.y = packh2(q1.x, q1.y);
        v.z = packh2(q2.x, q2.y);
        v.w = packh2(q3.x, q3.y);
        dst[fl] = v;
    }
}

// ================= fused gate/up + SiLU =================
// BM=128, BN=64 per matrix, BK=64. 8 warps: wm(4) x wn(2), warp tile 32x32 per matrix.
// B smem: [k 0..63][n 0..63] fp16, 128B rows, chunk swizzle c^=(k&7).
__global__ __launch_bounds__(NTHREADS, 2)
void moe_gateup(const uint4* __restrict__ xp, const float* __restrict__ w1,
                const float* __restrict__ w3, uint4* __restrict__ hp)
{
    extern __shared__ char smem[];
    const int tid = threadIdx.x, lane = tid & 31, wid = tid >> 5;
    const int wm = wid >> 1, wn = wid & 1;
    const int e = blockIdx.z, mt = blockIdx.y, nt = blockIdx.x;

    const uint4* xpe = xp + (long long)(e * 2 + mt) * 32 * 1024;
    const float* w1e = w1 + (long long)e * DIM * HIDDEN + nt * 64;
    const float* w3e = w3 + (long long)e * DIM * HIDDEN + nt * 64;

    uint4 u1[2], u3[2];  // staged packed rows

    auto ldgB = [&](int kt) {
#pragma unroll
        for (int j = 0; j < 2; j++) {
            int id = tid + 256 * j;
            int k = id >> 3, q = id & 7;
            const float* p1 = w1e + (long long)(kt + k) * HIDDEN + q * 8;
            float4 x0 = *(const float4*)p1;
            float4 x1 = *(const float4*)(p1 + 4);
            u1[j].x = packh2(x0.x, x0.y); u1[j].y = packh2(x0.z, x0.w);
            u1[j].z = packh2(x1.x, x1.y); u1[j].w = packh2(x1.z, x1.w);
            const float* p3 = w3e + (long long)(kt + k) * HIDDEN + q * 8;
            float4 y0 = *(const float4*)p3;
            float4 y1 = *(const float4*)(p3 + 4);
            u3[j].x = packh2(y0.x, y0.y); u3[j].y = packh2(y0.z, y0.w);
            u3[j].z = packh2(y1.x, y1.y); u3[j].w = packh2(y1.z, y1.w);
        }
    };
    auto stsB = [&](int buf) {
        char* b1 = smem + B_BASE + buf * 16384;
#pragma unroll
        for (int j = 0; j < 2; j++) {
            int id = tid + 256 * j;
            int k = id >> 3, q = id & 7;
            uint32_t off = (uint32_t)k * 128 + ((q ^ (k & 7)) * 16);
            *(uint4*)(b1 + off) = u1[j];
            *(uint4*)(b1 + 8192 + off) = u3[j];
        }
    };
    auto ldA = [&](int stage, int buf) {
        uint32_t sA = smem_u32(smem) + buf * A_PK;
        const uint4* src = xpe + (long long)stage * 1024;
#pragma unroll
        for (int j = 0; j < 4; j++) {
            int idx = tid + 256 * j;
            cp_async16(sA + idx * 16, src + idx);
        }
        cp_commit();
    };

    // ldmatrix lane bases (loop-invariant): kk0 = k-within-16, oct pair select
    const uint32_t kk0 = (lane & 7) + ((lane >> 3) & 1) * 8;
    uint32_t lmb[2];
#pragma unroll
    for (int q = 0; q < 2; q++) {
        uint32_t oct = (uint32_t)(wn * 4 + 2 * q) + (lane >> 4);
        lmb[q] = kk0 * 128 + ((oct ^ (kk0 & 7)) * 16);
    }

    float accG[2][4][4] = {}, accU[2][4][4] = {};

    ldgB(0);
    ldA(0, 0);
    ldA(1, 1);
    stsB(0);
    ldgB(64);
    cp_wait<1>();
    __syncthreads();

    const int NIT = DIM / 64;  // 32
    int a3 = 0, a3n = 2;
    for (int it = 0; it < NIT; ++it) {
        const int b = it & 1;
        if (it + 2 < NIT) ldA(it + 2, a3n);

        const uint4* Ap = (const uint4*)(smem + a3 * A_PK);
        const uint32_t Bb = smem_u32(smem) + B_BASE + b * 16384;

#pragma unroll
        for (int s = 0; s < 4; s++) {
            uint32_t a[2][4];
            {
                uint4 t0 = Ap[((2 * wm + 0) * 4 + s) * 32 + lane];
                uint4 t1 = Ap[((2 * wm + 1) * 4 + s) * 32 + lane];
                a[0][0] = t0.x; a[0][1] = t0.y; a[0][2] = t0.z; a[0][3] = t0.w;
                a[1][0] = t1.x; a[1][1] = t1.y; a[1][2] = t1.z; a[1][3] = t1.w;
            }
#pragma unroll
            for (int q = 0; q < 2; q++) {
                uint32_t addr = Bb + lmb[q] + (uint32_t)s * 2048;
                uint32_t r0, r1, r2, r3, c0, c1, c2, c3;
                ldm_x4t(r0, r1, r2, r3, addr);          // B1: frags 2q, 2q+1
                ldm_x4t(c0, c1, c2, c3, addr + 8192);   // B3
                mma_f16(accG[0][2 * q], a[0], r0, r1);
                mma_f16(accG[1][2 * q], a[1], r0, r1);
                mma_f16(accG[0][2 * q + 1], a[0], r2, r3);
                mma_f16(accG[1][2 * q + 1], a[1], r2, r3);
                mma_f16(accU[0][2 * q], a[0], c0, c1);
                mma_f16(accU[1][2 * q], a[1], c0, c1);
                mma_f16(accU[0][2 * q + 1], a[0], c2, c3);
                mma_f16(accU[1][2 * q + 1], a[1], c2, c3);
            }
        }
        if (it + 1 < NIT) stsB(1 - b);
        if (it + 2 < NIT) { ldgB((it + 2) * 64); cp_wait<1>(); }
        else cp_wait<0>();
        if (it + 1 < NIT) __syncthreads();
        a3 = (a3 == 2) ? 0 : a3 + 1;
        a3n = (a3n == 2) ? 0 : a3n + 1;
    }

    // epilogue: h = silu(gate)*up -> fp16, fragment-packed, coalesced uint4 stores
    uint4* hpe = hp + ((long long)(e * 2 + mt) * 16 + nt) * 1024;
#pragma unroll
    for (int mi = 0; mi < 2; mi++) {
#pragma unroll
        for (int nip = 0; nip < 2; nip++) {
            float hv[2][4];
#pragma unroll
            for (int q = 0; q < 2; q++) {
                int ni = 2 * nip + q;
#pragma unroll
                for (int j = 0; j < 4; j++) {
                    float gv = accG[mi][ni][j], uv = accU[mi][ni][j];
                    hv[q][j] = gv / (1.f + __expf(-gv)) * uv;
                }
            }
            uint4 v;
            v.x = packh2(hv[0][0], hv[0][1]);
            v.y = packh2(hv[0][2], hv[0][3]);
            v.z = packh2(hv[1][0], hv[1][1]);
            v.w = packh2(hv[1][2], hv[1][3]);
            int f_dn = (wm * 2 + mi) * 4 + (wn * 2 + nip);
            hpe[f_dn * 32 + lane] = v;
        }
    }
}

// ================= down-projection =================
// BM=128, BN=128, BK=64. Warp tile 32x64.
// B smem: [k 0..63][n 0..127] fp16, 256B rows, chunk swizzle c^=(k&7).
__global__ __launch_bounds__(NTHREADS, 2)
void moe_down(const uint4* __restrict__ hp, const float* __restrict__ w2,
              float* __restrict__ out)
{
    extern __shared__ char smem[];
    const int tid = threadIdx.x, lane = tid & 31, wid = tid >> 5;
    const int wm = wid >> 1, wn = wid & 1, g = lane >> 2, c = lane & 3;
    const int e = blockIdx.z, mt = blockIdx.y, nt = blockIdx.x;

    const uint4* hpe = hp + (long long)(e * 2 + mt) * 16 * 1024;
    const float* w2e = w2 + (long long)e * HIDDEN * DIM + nt * 128;

    uint4 u[4];  // staged packed rows

    auto ldgB = [&](int kt) {
#pragma unroll
        for (int j = 0; j < 4; j++) {
            int id = tid + 256 * j;
            int k = id >> 4, q = id & 15;
            const float* p = w2e + (long long)(kt + k) * DIM + q * 8;
            float4 x0 = *(const float4*)p;
            float4 x1 = *(const float4*)(p + 4);
            u[j].x = packh2(x0.x, x0.y); u[j].y = packh2(x0.z, x0.w);
            u[j].z = packh2(x1.x, x1.y); u[j].w = packh2(x1.z, x1.w);
        }
    };
    auto stsB = [&](int buf) {
        char* bb = smem + B_BASE + buf * 16384;
#pragma unroll
        for (int j = 0; j < 4; j++) {
            int id = tid + 256 * j;
            int k = id >> 4, q = id & 15;
            uint32_t off = (uint32_t)k * 256 + ((q ^ (k & 7)) * 16);
            *(uint4*)(bb + off) = u[j];
        }
    };
    auto ldA = [&](int stage, int buf) {
        uint32_t sA = smem_u32(smem) + buf * A_PK;
        const uint4* src = hpe + (long long)stage * 1024;
#pragma unroll
        for (int j = 0; j < 4; j++) {
            int idx = tid + 256 * j;
            cp_async16(sA + idx * 16, src + idx);
        }
        cp_commit();
    };

    // ldmatrix lane bases
    const uint32_t kk0 = (lane & 7) + ((lane >> 3) & 1) * 8;
    uint32_t lmb[4];
#pragma unroll
    for (int q = 0; q < 4; q++) {
        uint32_t oct = (uint32_t)(wn * 8 + 2 * q) + (lane >> 4);
        lmb[q] = kk0 * 256 + ((oct ^ (kk0 & 7)) * 16);
    }

    float acc[2][8][4] = {};

    ldgB(0);
    ldA(0, 0);
    ldA(1, 1);
    stsB(0);
    ldgB(64);
    cp_wait<1>();
    __syncthreads();

    const int NIT = HIDDEN / 64;  // 16
    int a3 = 0, a3n = 2;
    for (int it = 0; it < NIT; ++it) {
        const int b = it & 1;
        if (it + 2 < NIT) ldA(it + 2, a3n);

        const uint4* Ap = (const uint4*)(smem + a3 * A_PK);
        const uint32_t Bb = smem_u32(smem) + B_BASE + b * 16384;

#pragma unroll
        for (int s = 0; s < 4; s++) {
            uint32_t a[2][4];
            {
                uint4 t0 = Ap[((2 * wm + 0) * 4 + s) * 32 + lane];
                uint4 t1 = Ap[((2 * wm + 1) * 4 + s) * 32 + lane];
                a[0][0] = t0.x; a[0][1] = t0.y; a[0][2] = t0.z; a[0][3] = t0.w;
                a[1][0] = t1.x; a[1][1] = t1.y; a[1][2] = t1.z; a[1][3] = t1.w;
            }
#pragma unroll
            for (int q = 0; q < 4; q++) {
                uint32_t r0, r1, r2, r3;
                ldm_x4t(r0, r1, r2, r3, Bb + lmb[q] + (uint32_t)s * 4096);
                mma_f16(acc[0][2 * q], a[0], r0, r1);
                mma_f16(acc[1][2 * q], a[1], r0, r1);
                mma_f16(acc[0][2 * q + 1], a[0], r2, r3);
                mma_f16(acc[1][2 * q + 1], a[1], r2, r3);
            }
        }
        if (it + 1 < NIT) stsB(1 - b);
        if (it + 2 < NIT) { ldgB((it + 2) * 64); cp_wait<1>(); }
        else cp_wait<0>();
        if (it + 1 < NIT) __syncthreads();
        a3 = (a3 == 2) ? 0 : a3 + 1;
        a3n = (a3n == 2) ? 0 : a3n + 1;
    }

    const int colbase = nt * 128 + wn * 64;
    const long long rowbase = (long long)e * TOK_PER_E + mt * 128 + wm * 32;
#pragma unroll
    for (int mi = 0; mi < 2; mi++) {
        const long long r0 = rowbase + mi * 16 + g;
#pragma unroll
        for (int ni = 0; ni < 8; ni++) {
            const int col = colbase + ni * 8 + 2 * c;
            float* p0 = out + r0 * DIM + col;
            float* p1 = p0 + 8 * DIM;
            *(float2*)p0 = make_float2(acc[mi][ni][0], acc[mi][ni][1]);
            *(float2*)p1 = make_float2(acc[mi][ni][2], acc[mi][ni][3]);
        }
    }
}

// ================= launch =================
extern "C" void kernel_launch(void* const* d_in, const int* in_sizes, int n_in,
                              void* d_out, int out_size)
{
    const float* x  = (const float*)d_in[0];
    const float* w1 = (const float*)d_in[1];
    const float* w2 = (const float*)d_in[2];
    const float* w3 = (const float*)d_in[3];
    float* out = (float*)d_out;

    uint4* xp = nullptr;
    uint4* hp = nullptr;
    cudaGetSymbolAddress((void**)&xp, g_xp);
    cudaGetSymbolAddress((void**)&hp, g_hp);

    static bool attr_done = false;
    if (!attr_done) {
        cudaFuncSetAttribute(moe_gateup, cudaFuncAttributeMaxDynamicSharedMemorySize, SMEM_TOT);
        cudaFuncSetAttribute(moe_down, cudaFuncAttributeMaxDynamicSharedMemorySize, SMEM_TOT);
        attr_done = true;
    }

    {
        dim3 grid(DIM / 64, TOK_PER_E / 128, NUM_EXPERTS);     // (32, 2, 64)
        xpack_kernel<<<grid, NTHREADS>>>(x, xp);
    }
    {
        dim3 grid(HIDDEN / 64, TOK_PER_E / 128, NUM_EXPERTS);  // (16, 2, 64)
        moe_gateup<<<grid, NTHREADS, SMEM_TOT>>>(xp, w1, w3, hp);
    }
    {
        dim3 grid(DIM / 128, TOK_PER_E / 128, NUM_EXPERTS);    // (16, 2, 64)
        moe_down<<<grid, NTHREADS, SMEM_TOT>>>(hp, w2, out);
    }
}